// round 16
// baseline (speedup 1.0000x reference)
#include <cuda_runtime.h>
#include <cuda_bf16.h>
#include <math.h>
#include <stdint.h>

#define B   4096
#define L   200
#define LF  100
#define E   64
#define P   32
#define H   32
#define IFD 128
#define TPD 3168   /* P + PNET = 32 + 3136 */

typedef unsigned long long ull;

// ---------- bf16 helpers ----------
__device__ __forceinline__ uint32_t packbf(float x, float y) {
    __nv_bfloat162 h = __floats2bfloat162_rn(x, y);
    return *(uint32_t*)&h;
}
__device__ __forceinline__ float bflo(float v) {
    return v - __bfloat162float(__float2bfloat16(v));
}

// HMMA m16n8k16 bf16
__device__ __forceinline__ void hmma(float* c, uint32_t a0, uint32_t a1, uint32_t a2, uint32_t a3,
                                     uint32_t b0, uint32_t b1) {
    asm volatile(
        "mma.sync.aligned.m16n8k16.row.col.f32.bf16.bf16.f32 "
        "{%0,%1,%2,%3}, {%4,%5,%6,%7}, {%8,%9}, {%0,%1,%2,%3};"
        : "+f"(c[0]), "+f"(c[1]), "+f"(c[2]), "+f"(c[3])
        : "r"(a0), "r"(a1), "r"(a2), "r"(a3), "r"(b0), "r"(b1));
}

// ---------------- scratch (device globals) ----------------
__device__ float g_prompt_input[B * E];
__device__ float g_total_prompt[(size_t)B * TPD];        // ~52 MB
__device__ float g_final_user[B * E];
__device__ float g_final_item[B * E];
__device__ float g_pos_pe[B * P];
__device__ float g_neg_pe[B * P];
__device__ float g_ife[B * E];
__device__ float g_ufe[B * E];

// ======================================================================
// K0: batched feature MLPs
// ======================================================================
__global__ __launch_bounds__(256) void k0_kernel(
    const float* __restrict__ item_features, const float* __restrict__ user_features,
    const float* __restrict__ W_if, const float* __restrict__ b_if,
    const float* __restrict__ W_uf, const float* __restrict__ b_uf)
{
    int b0 = blockIdx.x * 32;
    int tid = threadIdx.x;
    __shared__ float sW[IFD * E];
    __shared__ float sF[4 * IFD];
    int rr = tid >> 6, out = tid & 63;

    #pragma unroll
    for (int ph = 0; ph < 2; ph++) {
        const float* W    = ph ? W_uf : W_if;
        const float* bias = ph ? b_uf : b_if;
        const float* F    = ph ? user_features : item_features;
        float* dst        = ph ? g_ufe : g_ife;

        __syncthreads();
        for (int t = tid; t < IFD * E; t += 256) sW[t] = W[t];

        for (int rg = 0; rg < 8; rg++) {
            __syncthreads();
            for (int t = tid; t < 4 * IFD; t += 256)
                sF[t] = F[(size_t)(b0 + rg * 4 + (t >> 7)) * IFD + (t & 127)];
            __syncthreads();
            float acc = bias[out];
            #pragma unroll
            for (int c = 0; c < 32; c++) {
                float4 f = *(const float4*)&sF[rr * IFD + c * 4];
                acc += f.x * sW[(c*4+0) * E + out] + f.y * sW[(c*4+1) * E + out]
                     + f.z * sW[(c*4+2) * E + out] + f.w * sW[(c*4+3) * E + out];
            }
            dst[(size_t)(b0 + rg * 4 + rr) * E + out] = 1.0f / (1.0f + expf(-acc));
        }
    }
}

// ======================================================================
// K1p: prompt pooling only -> g_prompt_input
// ======================================================================
__global__ __launch_bounds__(256) void k1p_kernel(
    const float* __restrict__ item_emb,
    const int* __restrict__ item_pos_feedback, const int* __restrict__ pos_mask)
{
    int b = blockIdx.x;
    int tid = threadIdx.x;
    __shared__ int   s_pidx[LF];
    __shared__ float s_pm[LF];
    __shared__ float red[256];

    for (int l = tid; l < LF; l += 256) {
        s_pidx[l] = item_pos_feedback[(size_t)b * LF + l];
        s_pm[l]   = pos_mask[(size_t)b * LF + l] ? 1.0f : 0.0f;
    }
    __syncthreads();

    int g = tid >> 6, e = tid & 63;
    float pacc = 0.0f;
    int base = g * 25;
    #pragma unroll 5
    for (int l = base; l < base + 25; l++)
        pacc += s_pm[l] * item_emb[(size_t)s_pidx[l] * E + e];
    red[tid] = pacc;
    __syncthreads();
    if (tid < 64) {
        float s = red[tid] + red[64 + tid] + red[128 + tid] + red[192 + tid];
        float cnt = 0.0f;
        #pragma unroll 10
        for (int l = 0; l < LF; l++) cnt += s_pm[l];
        g_prompt_input[b * E + tid] = s / cnt;
    }
}

// ======================================================================
// K1a v2: flash-style chunked attention (2 x 100), ~27 KB smem.
// ======================================================================
#define CSH 105
__global__ __launch_bounds__(256) void k1a_kernel(
    const float* __restrict__ item_emb, const float* __restrict__ user_emb,
    const int* __restrict__ user_id, const int* __restrict__ target_item_id,
    const int* __restrict__ history_item_id, const int* __restrict__ history_len)
{
    extern __shared__ float SHT[];   // [64][105]
    int b = blockIdx.x;
    int tid = threadIdx.x;

    __shared__ float s_tgt[E];
    __shared__ int   s_hidx[L];
    __shared__ float red[256];
    __shared__ float s_w[100];

    int tgt_id = target_item_id[b];
    if (tid < E) s_tgt[tid] = item_emb[(size_t)tgt_id * E + tid];
    for (int l = tid; l < L; l += 256) s_hidx[l] = history_item_id[(size_t)b * L + l];
    __syncthreads();

    int hlen = history_len[b];
    int g = tid >> 6, e = tid & 63;
    float accp = 0.0f;
    float m = -1e30f;
    float dsum = 0.0f;

    #pragma unroll
    for (int ch = 0; ch < 2; ch++) {
        for (int idx = tid; idx < 100 * 16; idx += 256) {
            int l = idx >> 4, c4 = idx & 15;
            float4 v = *(const float4*)(item_emb + (size_t)s_hidx[ch * 100 + l] * E + c4 * 4);
            SHT[(4*c4+0) * CSH + l] = v.x;
            SHT[(4*c4+1) * CSH + l] = v.y;
            SHT[(4*c4+2) * CSH + l] = v.z;
            SHT[(4*c4+3) * CSH + l] = v.w;
        }
        __syncthreads();

        float sc = -1e30f;
        if (tid < 100) {
            float d = 0.0f;
            #pragma unroll 8
            for (int e2 = 0; e2 < E; e2++)
                d += SHT[e2 * CSH + tid] * s_tgt[e2];
            int gl = ch * 100 + tid;
            sc = (gl < hlen) ? d * 0.125f : -1e9f;
        }
        red[tid] = sc; __syncthreads();
        for (int s = 128; s > 0; s >>= 1) { if (tid < s) red[tid] = fmaxf(red[tid], red[tid+s]); __syncthreads(); }
        float mnew = fmaxf(m, red[0]);
        __syncthreads();
        float wv = (tid < 100) ? expf(sc - mnew) : 0.0f;
        if (tid < 100) s_w[tid] = wv;
        red[tid] = wv; __syncthreads();
        for (int s = 128; s > 0; s >>= 1) { if (tid < s) red[tid] += red[tid+s]; __syncthreads(); }
        float wsum = red[0];
        __syncthreads();

        float scale = expf(m - mnew);
        dsum = dsum * scale + wsum;
        float a = 0.0f;
        int base = g * 25;
        #pragma unroll 5
        for (int l = base; l < base + 25; l++)
            a += s_w[l] * SHT[e * CSH + l];
        accp = accp * scale + a;
        m = mnew;
        __syncthreads();
    }

    red[tid] = accp;
    __syncthreads();
    if (tid < 64) {
        float hp = (red[tid] + red[64 + tid] + red[128 + tid] + red[192 + tid]) / dsum;
        int uid = user_id[b];
        g_final_user[b * E + tid] = user_emb[(size_t)uid * E + tid] + g_ufe[b * E + tid] + hp;
        g_final_item[b * E + tid] = item_emb[(size_t)tgt_id * E + tid] + g_ife[b * E + tid];
    }
}

// ======================================================================
// K2 v6: HMMA bf16-split GEMM, 4 row-groups per block (B tile reused 4x).
// grid (16, 25). Block covers 256 rows x 128 cols.
// ======================================================================
#define K2_AHI  0
#define K2_ALO  2304
#define K2_BHI  4608
#define K2_BLO  9216
#define K2_DYNW 13824   /* words = 55296 B */

__global__ __launch_bounds__(256) void k2_kernel(
    const float* __restrict__ Wp, const float* __restrict__ bp)
{
    extern __shared__ __align__(16) uint32_t SW[];
    int jb = blockIdx.y * 128;
    int tid = threadIdx.x;
    __shared__ float sbias[128];

    // B: Wp[k][jb+n] -> Bn[n][k] hi/lo (loaded ONCE, reused by 4 rg)
    for (int idx = tid; idx < 32 * 128; idx += 256) {
        int kk = idx >> 7, n = idx & 127;
        int j = jb + n;
        float v0 = 0.0f, v1 = 0.0f;
        if (j < TPD) {
            v0 = Wp[(size_t)(2*kk)     * TPD + j];
            v1 = Wp[(size_t)(2*kk + 1) * TPD + j];
        }
        SW[K2_BHI + n * 36 + kk] = packbf(v0, v1);
        SW[K2_BLO + n * 36 + kk] = packbf(bflo(v0), bflo(v1));
    }
    if (tid < 128) {
        int j = jb + tid;
        sbias[tid] = (j < TPD) ? bp[j] : 0.0f;
    }

    int w = tid >> 5, lane = tid & 31;
    int g = lane >> 2, t = lane & 3;
    int mt = w & 3;
    int half = w >> 2;
    int R = mt * 16;

    #pragma unroll
    for (int rg = 0; rg < 4; rg++) {
        int b0 = (blockIdx.x * 4 + rg) * 64;
        if (rg) __syncthreads();
        for (int idx = tid; idx < 64 * 16; idx += 256) {
            int i = idx >> 4, c4 = idx & 15;
            float4 v = *(const float4*)&g_prompt_input[(b0 + i) * E + c4 * 4];
            int rb = i * 36 + 2 * c4;
            SW[K2_AHI + rb]     = packbf(v.x, v.y);
            SW[K2_AHI + rb + 1] = packbf(v.z, v.w);
            SW[K2_ALO + rb]     = packbf(bflo(v.x), bflo(v.y));
            SW[K2_ALO + rb + 1] = packbf(bflo(v.z), bflo(v.w));
        }
        __syncthreads();

        float acc[8][4];
        #pragma unroll
        for (int nt = 0; nt < 8; nt++)
            #pragma unroll
            for (int j = 0; j < 4; j++) acc[nt][j] = 0.0f;

        #pragma unroll
        for (int k = 0; k < 4; k++) {
            int o0 = (R + g) * 36 + 8*k + t;
            int o1 = (R + g + 8) * 36 + 8*k + t;
            uint32_t a0 = SW[K2_AHI + o0], a1 = SW[K2_AHI + o1];
            uint32_t a2 = SW[K2_AHI + o0 + 4], a3 = SW[K2_AHI + o1 + 4];
            uint32_t l0 = SW[K2_ALO + o0], l1 = SW[K2_ALO + o1];
            uint32_t l2 = SW[K2_ALO + o0 + 4], l3 = SW[K2_ALO + o1 + 4];
            #pragma unroll
            for (int nt = 0; nt < 8; nt++) {
                int n = half * 64 + nt * 8 + g;
                uint32_t b0r = SW[K2_BHI + n * 36 + 8*k + t];
                uint32_t b1r = SW[K2_BHI + n * 36 + 8*k + t + 4];
                uint32_t c0 = SW[K2_BLO + n * 36 + 8*k + t];
                uint32_t c1 = SW[K2_BLO + n * 36 + 8*k + t + 4];
                hmma(acc[nt], a0, a1, a2, a3, b0r, b1r);
                hmma(acc[nt], l0, l1, l2, l3, b0r, b1r);
                hmma(acc[nt], a0, a1, a2, a3, c0, c1);
            }
        }

        #pragma unroll
        for (int nt = 0; nt < 8; nt++) {
            int c = half * 64 + nt * 8 + 2 * t;
            int j = jb + c;
            if (j < TPD) {
                float bz0 = sbias[c], bz1 = sbias[c + 1];
                float2 v0, v1;
                v0.x = fmaxf(acc[nt][0] + bz0, 0.0f);
                v0.y = fmaxf(acc[nt][1] + bz1, 0.0f);
                v1.x = fmaxf(acc[nt][2] + bz0, 0.0f);
                v1.y = fmaxf(acc[nt][3] + bz1, 0.0f);
                *(float2*)&g_total_prompt[(size_t)(b0 + R + g) * TPD + j]     = v0;
                *(float2*)&g_total_prompt[(size_t)(b0 + R + g + 8) * TPD + j] = v1;
            }
        }
    }
}

// ======================================================================
// K3 v11: merged pos+neg (224 rows), streamed A chunks, shared W pack.
// One block per sample. 14 m-tiles: warp w takes tiles {w, 8+w} (2nd if w<6).
// Rows 0..111 pos (104 valid), 112..223 neg.
// Layout (words): A chunk hi 0 / lo 4032 (8064); H hi 0 / lo 4480 (8960,
// aliases A); W1 8960/10112; W2 11264/11904; total 12544 w = 50176 B.
// ======================================================================
#define K3_ALO   4032
#define K3_HLO   4480
#define K3_W1HI  8960
#define K3_W1LO  10112
#define K3_W2HI  11264
#define K3_W2LO  11904
#define K3_DYNW  12544

__global__ __launch_bounds__(256) void k3_kernel(
    const float* __restrict__ item_emb,
    const int* __restrict__ pos_fb, const int* __restrict__ pos_mask,
    const int* __restrict__ neg_fb, const int* __restrict__ neg_mask)
{
    extern __shared__ __align__(16) uint32_t SW[];
    int b = blockIdx.x;
    int tid = threadIdx.x;
    const float* tp = g_total_prompt + (size_t)b * TPD;

    __shared__ int   s_fi[224];
    __shared__ float s_fm[224];
    __shared__ float b1s[32], b2s[32];
    __shared__ float RED[14][32];

    if (tid < 224) {
        int br = tid >= 112;
        int l  = tid - br * 112;
        int v = 0; float m = 0.0f;
        if (l < LF) {
            const int* fb = br ? neg_fb : pos_fb;
            const int* mk = br ? neg_mask : pos_mask;
            v = fb[(size_t)b * LF + l];
            m = mk[(size_t)b * LF + l] ? 1.0f : 0.0f;
        }
        s_fi[tid] = v; s_fm[tid] = m;
    }
    if (tid < 32) { b1s[tid] = tp[2080 + tid]; b2s[tid] = tp[3136 + tid]; }

    // W packs (region disjoint from A chunks -> done once)
    for (int idx = tid; idx < 1024; idx += 256) {
        int h = idx & 31, ep = idx >> 5;
        float v0 = tp[32 + (2*ep)     * 32 + h];
        float v1 = tp[32 + (2*ep + 1) * 32 + h];
        SW[K3_W1HI + h * 36 + ep] = packbf(v0, v1);
        SW[K3_W1LO + h * 36 + ep] = packbf(bflo(v0), bflo(v1));
    }
    for (int idx = tid; idx < 512; idx += 256) {
        int p = idx & 31, hp = idx >> 5;
        float v0 = tp[2112 + (2*hp)     * 32 + p];
        float v1 = tp[2112 + (2*hp + 1) * 32 + p];
        SW[K3_W2HI + p * 20 + hp] = packbf(v0, v1);
        SW[K3_W2LO + p * 20 + hp] = packbf(bflo(v0), bflo(v1));
    }
    __syncthreads();

    int w = tid >> 5, lane = tid & 31;
    int g = lane >> 2, t = lane & 3;
    int ntl = (w < 6) ? 2 : 1;
    int tiles[2] = { w, 8 + w };

    // ---------------- layer 1, streamed over 2 e-chunks ----------------
    float acc1[2][4][4];
    #pragma unroll
    for (int ti = 0; ti < 2; ti++)
        #pragma unroll
        for (int nt = 0; nt < 4; nt++)
            #pragma unroll
            for (int j = 0; j < 4; j++) acc1[ti][nt][j] = 0.0f;

    #pragma unroll
    for (int ch = 0; ch < 2; ch++) {
        if (ch) __syncthreads();
        for (int idx = tid; idx < 224 * 8; idx += 256) {
            int i = idx >> 3, c4 = idx & 7;
            float4 v = *(const float4*)(item_emb + (size_t)s_fi[i] * E + ch * 32 + c4 * 4);
            int rb = i * 18 + 2 * c4;
            SW[rb]     = packbf(v.x, v.y);
            SW[rb + 1] = packbf(v.z, v.w);
            SW[K3_ALO + rb]     = packbf(bflo(v.x), bflo(v.y));
            SW[K3_ALO + rb + 1] = packbf(bflo(v.z), bflo(v.w));
        }
        __syncthreads();

        for (int ti = 0; ti < ntl; ti++) {
            int R = tiles[ti] * 16;
            #pragma unroll
            for (int k = 0; k < 2; k++) {
                int o0 = (R + g) * 18 + 8*k + t;
                int o1 = (R + g + 8) * 18 + 8*k + t;
                uint32_t a0 = SW[o0], a1 = SW[o1];
                uint32_t a2 = SW[o0 + 4], a3 = SW[o1 + 4];
                uint32_t l0 = SW[K3_ALO + o0], l1 = SW[K3_ALO + o1];
                uint32_t l2 = SW[K3_ALO + o0 + 4], l3 = SW[K3_ALO + o1 + 4];
                int eo = 8 * (2 * ch + k) + t;
                #pragma unroll
                for (int nt = 0; nt < 4; nt++) {
                    int n = nt * 8 + g;
                    uint32_t b0 = SW[K3_W1HI + n * 36 + eo];
                    uint32_t b1 = SW[K3_W1HI + n * 36 + eo + 4];
                    uint32_t c0 = SW[K3_W1LO + n * 36 + eo];
                    uint32_t c1 = SW[K3_W1LO + n * 36 + eo + 4];
                    hmma(acc1[ti][nt], a0, a1, a2, a3, b0, b1);
                    hmma(acc1[ti][nt], l0, l1, l2, l3, b0, b1);
                    hmma(acc1[ti][nt], a0, a1, a2, a3, c0, c1);
                }
            }
        }
    }
    __syncthreads();   // A reads done; region becomes H

    // ---- epilogue 1: relu(D1 + b1) -> Hhi/Hlo ----
    for (int ti = 0; ti < ntl; ti++) {
        int R = tiles[ti] * 16;
        #pragma unroll
        for (int nt = 0; nt < 4; nt++) {
            int c = nt * 8 + 2 * t;
            float h00 = fmaxf(acc1[ti][nt][0] + b1s[c],     0.0f);
            float h01 = fmaxf(acc1[ti][nt][1] + b1s[c + 1], 0.0f);
            float h10 = fmaxf(acc1[ti][nt][2] + b1s[c],     0.0f);
            float h11 = fmaxf(acc1[ti][nt][3] + b1s[c + 1], 0.0f);
            int w0 = (R + g) * 20 + nt * 4 + t;
            int w1 = (R + g + 8) * 20 + nt * 4 + t;
            SW[w0] = packbf(h00, h01);
            SW[w1] = packbf(h10, h11);
            SW[K3_HLO + w0] = packbf(bflo(h00), bflo(h01));
            SW[K3_HLO + w1] = packbf(bflo(h10), bflo(h11));
        }
    }
    __syncthreads();

    // ---------------- layer 2 ----------------
    float acc2[2][4][4];
    #pragma unroll
    for (int ti = 0; ti < 2; ti++)
        #pragma unroll
        for (int nt = 0; nt < 4; nt++)
            #pragma unroll
            for (int j = 0; j < 4; j++) acc2[ti][nt][j] = 0.0f;

    for (int ti = 0; ti < ntl; ti++) {
        int R = tiles[ti] * 16;
        #pragma unroll
        for (int k = 0; k < 2; k++) {
            int o0 = (R + g) * 20 + 8*k + t;
            int o1 = (R + g + 8) * 20 + 8*k + t;
            uint32_t a0 = SW[o0], a1 = SW[o1];
            uint32_t a2 = SW[o0 + 4], a3 = SW[o1 + 4];
            uint32_t l0 = SW[K3_HLO + o0], l1 = SW[K3_HLO + o1];
            uint32_t l2 = SW[K3_HLO + o0 + 4], l3 = SW[K3_HLO + o1 + 4];
            #pragma unroll
            for (int nt = 0; nt < 4; nt++) {
                int n = nt * 8 + g;
                uint32_t b0 = SW[K3_W2HI + n * 20 + 8*k + t];
                uint32_t b1 = SW[K3_W2HI + n * 20 + 8*k + t + 4];
                uint32_t c0 = SW[K3_W2LO + n * 20 + 8*k + t];
                uint32_t c1 = SW[K3_W2LO + n * 20 + 8*k + t + 4];
                hmma(acc2[ti][nt], a0, a1, a2, a3, b0, b1);
                hmma(acc2[ti][nt], l0, l1, l2, l3, b0, b1);
                hmma(acc2[ti][nt], a0, a1, a2, a3, c0, c1);
            }
        }
    }

    // ---- epilogue 2: masked sum per tile ----
    for (int ti = 0; ti < ntl; ti++) {
        int tt = tiles[ti];
        int R = tt * 16;
        float m0 = s_fm[R + g], m1 = s_fm[R + g + 8];
        float part[4][2];
        #pragma unroll
        for (int nt = 0; nt < 4; nt++) {
            int c = nt * 8 + 2 * t;
            part[nt][0] = m0 * (acc2[ti][nt][0] + b2s[c])   + m1 * (acc2[ti][nt][2] + b2s[c]);
            part[nt][1] = m0 * (acc2[ti][nt][1] + b2s[c+1]) + m1 * (acc2[ti][nt][3] + b2s[c+1]);
        }
        #pragma unroll
        for (int s = 4; s <= 16; s <<= 1) {
            #pragma unroll
            for (int nt = 0; nt < 4; nt++) {
                part[nt][0] += __shfl_xor_sync(0xffffffffu, part[nt][0], s);
                part[nt][1] += __shfl_xor_sync(0xffffffffu, part[nt][1], s);
            }
        }
        if (lane < 4) {
            #pragma unroll
            for (int nt = 0; nt < 4; nt++) {
                RED[tt][nt * 8 + 2 * lane]     = part[nt][0];
                RED[tt][nt * 8 + 2 * lane + 1] = part[nt][1];
            }
        }
    }
    __syncthreads();
    if (tid < 32) {
        float pos = 0.0f, neg = 0.0f;
        #pragma unroll
        for (int q = 0; q < 7; q++)  pos += RED[q][tid];
        #pragma unroll
        for (int q = 7; q < 14; q++) neg += RED[q][tid];
        g_pos_pe[b * 32 + tid] = pos;
        g_neg_pe[b * 32 + tid] = neg;
    }
}

// ======================================================================
// K4: loss + fusion MLP + dot. 4 rows/block.
// ======================================================================
__global__ __launch_bounds__(256) void k4_kernel(
    const float* __restrict__ Wf1, const float* __restrict__ bf1,
    const float* __restrict__ Wf2, const float* __restrict__ bf2,
    const float* __restrict__ Wf3, float* __restrict__ out)
{
    int b0 = blockIdx.x * 4;
    int tid = threadIdx.x;
    __shared__ float fin[4 * 128];
    __shared__ float h1[4 * 200];
    __shared__ float h2[4 * 80];
    __shared__ float fu[4 * 64];

    if (tid < 128) {
        int r = tid >> 5, c = tid & 31;
        int bb = b0 + r;
        float pos = g_pos_pe[bb * 32 + c];
        float neg = g_neg_pe[bb * 32 + c];
        float x = neg - pos;
        out[B + bb * 32 + c] = fmaxf(x, 0.0f) + log1pf(expf(-fabsf(x)));
    }

    for (int t = tid; t < 4 * 128; t += 256) {
        int r = t >> 7, c = t & 127;
        int bb = b0 + r;
        float v;
        if (c < 64)      v = g_final_item[bb * 64 + c];
        else if (c < 96) v = g_pos_pe[bb * 32 + (c - 64)];
        else             v = g_total_prompt[(size_t)bb * TPD + (c - 96)];
        fin[t] = v;
    }
    __syncthreads();

    if (tid < 200) {
        float acc[4];
        #pragma unroll
        for (int r = 0; r < 4; r++) acc[r] = bf1[tid];
        #pragma unroll 4
        for (int k = 0; k < 128; k++) {
            float w = Wf1[k * 200 + tid];
            #pragma unroll
            for (int r = 0; r < 4; r++) acc[r] += fin[r * 128 + k] * w;
        }
        #pragma unroll
        for (int r = 0; r < 4; r++) h1[r * 200 + tid] = acc[r] > 0.0f ? acc[r] : 0.0f;
    }
    __syncthreads();

    if (tid < 80) {
        float acc[4];
        #pragma unroll
        for (int r = 0; r < 4; r++) acc[r] = bf2[tid];
        #pragma unroll 4
        for (int k = 0; k < 200; k++) {
            float w = Wf2[k * 80 + tid];
            #pragma unroll
            for (int r = 0; r < 4; r++) acc[r] += h1[r * 200 + k] * w;
        }
        #pragma unroll
        for (int r = 0; r < 4; r++) h2[r * 80 + tid] = acc[r] > 0.0f ? acc[r] : 0.0f;
    }
    __syncthreads();

    if (tid < 64) {
        float acc[4];
        #pragma unroll
        for (int r = 0; r < 4; r++) acc[r] = 0.0f;
        #pragma unroll 4
        for (int k = 0; k < 80; k++) {
            float w = Wf3[k * 64 + tid];
            #pragma unroll
            for (int r = 0; r < 4; r++) acc[r] += h2[r * 80 + k] * w;
        }
        #pragma unroll
        for (int r = 0; r < 4; r++) fu[r * 64 + tid] = acc[r];
    }
    __syncthreads();

    int r = tid >> 5, lane = tid & 31;
    if (r < 4) {
        int bb = b0 + r;
        float par = g_final_user[bb * 64 + lane]      * fu[r * 64 + lane]
                  + g_final_user[bb * 64 + 32 + lane] * fu[r * 64 + 32 + lane];
        #pragma unroll
        for (int s = 16; s > 0; s >>= 1) par += __shfl_xor_sync(0xffffffff, par, s);
        if (lane == 0) out[bb] = par;
    }
}

// ---------------- side stream + fork/join events ----------------
static cudaStream_t g_s2;
static cudaEvent_t  g_ev_fork, g_ev_join;
static bool g_init = []() {
    cudaStreamCreateWithFlags(&g_s2, cudaStreamNonBlocking);
    cudaEventCreateWithFlags(&g_ev_fork, cudaEventDisableTiming);
    cudaEventCreateWithFlags(&g_ev_join, cudaEventDisableTiming);
    return true;
}();

// ======================================================================
extern "C" void kernel_launch(void* const* d_in, const int* in_sizes, int n_in,
                              void* d_out, int out_size)
{
    const float* item_emb        = (const float*)d_in[0];
    const float* user_emb        = (const float*)d_in[1];
    const float* W_if            = (const float*)d_in[2];
    const float* b_if            = (const float*)d_in[3];
    const float* W_uf            = (const float*)d_in[4];
    const float* b_uf            = (const float*)d_in[5];
    const float* Wp              = (const float*)d_in[6];
    const float* bp              = (const float*)d_in[7];
    const float* Wf1             = (const float*)d_in[8];
    const float* bf1             = (const float*)d_in[9];
    const float* Wf2             = (const float*)d_in[10];
    const float* bf2             = (const float*)d_in[11];
    const float* Wf3             = (const float*)d_in[12];
    const float* item_features   = (const float*)d_in[13];
    const float* user_features   = (const float*)d_in[14];
    const int*   user_id         = (const int*)d_in[15];
    const int*   target_item_id  = (const int*)d_in[16];
    const int*   history_item_id = (const int*)d_in[17];
    const int*   history_len     = (const int*)d_in[18];
    const int*   pos_fb          = (const int*)d_in[19];
    const int*   pos_mask        = (const int*)d_in[20];
    const int*   neg_fb          = (const int*)d_in[21];
    const int*   neg_mask        = (const int*)d_in[22];
    float* out = (float*)d_out;

    const int k1a_dyn = 64 * CSH * sizeof(float);  // 26880 B
    const int k2_dyn  = K2_DYNW * 4;               // 55296 B
    const int k3_dyn  = K3_DYNW * 4;               // 50176 B
    cudaFuncSetAttribute(k1a_kernel, cudaFuncAttributeMaxDynamicSharedMemorySize, k1a_dyn);
    cudaFuncSetAttribute(k2_kernel,  cudaFuncAttributeMaxDynamicSharedMemorySize, k2_dyn);
    cudaFuncSetAttribute(k3_kernel,  cudaFuncAttributeMaxDynamicSharedMemorySize, k3_dyn);

    // fork: side chain {K0 -> K1a} runs concurrently with {K1p -> K2 -> K3}
    cudaEventRecord(g_ev_fork, 0);
    cudaStreamWaitEvent(g_s2, g_ev_fork, 0);

    k0_kernel<<<B / 32, 256, 0, g_s2>>>(item_features, user_features, W_if, b_if, W_uf, b_uf);
    k1a_kernel<<<B, 256, k1a_dyn, g_s2>>>(item_emb, user_emb, user_id, target_item_id,
                                          history_item_id, history_len);
    cudaEventRecord(g_ev_join, g_s2);

    k1p_kernel<<<B, 256>>>(item_emb, pos_fb, pos_mask);
    k2_kernel<<<dim3(16, 25), 256, k2_dyn>>>(Wp, bp);
    k3_kernel<<<B, 256, k3_dyn>>>(item_emb, pos_fb, pos_mask, neg_fb, neg_mask);

    // join: K4 needs both chains
    cudaStreamWaitEvent(0, g_ev_join, 0);
    k4_kernel<<<B / 4, 256>>>(Wf1, bf1, Wf2, bf2, Wf3, out);
}

// round 17
// speedup vs baseline: 1.2159x; 1.2159x over previous
#include <cuda_runtime.h>
#include <cuda_bf16.h>
#include <math.h>
#include <stdint.h>

#define B   4096
#define L   200
#define LF  100
#define E   64
#define P   32
#define H   32
#define IFD 128
#define TPD 3168   /* P + PNET = 32 + 3136 */

typedef unsigned long long ull;

// ---------- bf16 helpers ----------
__device__ __forceinline__ uint32_t packbf(float x, float y) {
    __nv_bfloat162 h = __floats2bfloat162_rn(x, y);
    return *(uint32_t*)&h;
}
__device__ __forceinline__ float bflo(float v) {
    return v - __bfloat162float(__float2bfloat16(v));
}

// HMMA m16n8k16 bf16
__device__ __forceinline__ void hmma(float* c, uint32_t a0, uint32_t a1, uint32_t a2, uint32_t a3,
                                     uint32_t b0, uint32_t b1) {
    asm volatile(
        "mma.sync.aligned.m16n8k16.row.col.f32.bf16.bf16.f32 "
        "{%0,%1,%2,%3}, {%4,%5,%6,%7}, {%8,%9}, {%0,%1,%2,%3};"
        : "+f"(c[0]), "+f"(c[1]), "+f"(c[2]), "+f"(c[3])
        : "r"(a0), "r"(a1), "r"(a2), "r"(a3), "r"(b0), "r"(b1));
}

// ---------------- scratch (device globals) ----------------
__device__ float g_prompt_input[B * E];
__device__ float g_total_prompt[(size_t)B * TPD];        // ~52 MB
__device__ float g_final_user[B * E];
__device__ float g_final_item[B * E];
__device__ float g_pos_pe[B * P];
__device__ float g_neg_pe[B * P];
__device__ float g_ife[B * E];
__device__ float g_ufe[B * E];

// ======================================================================
// K0: batched feature MLPs
// ======================================================================
__global__ __launch_bounds__(256) void k0_kernel(
    const float* __restrict__ item_features, const float* __restrict__ user_features,
    const float* __restrict__ W_if, const float* __restrict__ b_if,
    const float* __restrict__ W_uf, const float* __restrict__ b_uf)
{
    int b0 = blockIdx.x * 32;
    int tid = threadIdx.x;
    __shared__ float sW[IFD * E];
    __shared__ float sF[4 * IFD];
    int rr = tid >> 6, out = tid & 63;

    #pragma unroll
    for (int ph = 0; ph < 2; ph++) {
        const float* W    = ph ? W_uf : W_if;
        const float* bias = ph ? b_uf : b_if;
        const float* F    = ph ? user_features : item_features;
        float* dst        = ph ? g_ufe : g_ife;

        __syncthreads();
        for (int t = tid; t < IFD * E; t += 256) sW[t] = W[t];

        for (int rg = 0; rg < 8; rg++) {
            __syncthreads();
            for (int t = tid; t < 4 * IFD; t += 256)
                sF[t] = F[(size_t)(b0 + rg * 4 + (t >> 7)) * IFD + (t & 127)];
            __syncthreads();
            float acc = bias[out];
            #pragma unroll
            for (int c = 0; c < 32; c++) {
                float4 f = *(const float4*)&sF[rr * IFD + c * 4];
                acc += f.x * sW[(c*4+0) * E + out] + f.y * sW[(c*4+1) * E + out]
                     + f.z * sW[(c*4+2) * E + out] + f.w * sW[(c*4+3) * E + out];
            }
            dst[(size_t)(b0 + rg * 4 + rr) * E + out] = 1.0f / (1.0f + expf(-acc));
        }
    }
}

// ======================================================================
// K1p: prompt pooling only -> g_prompt_input
// ======================================================================
__global__ __launch_bounds__(256) void k1p_kernel(
    const float* __restrict__ item_emb,
    const int* __restrict__ item_pos_feedback, const int* __restrict__ pos_mask)
{
    int b = blockIdx.x;
    int tid = threadIdx.x;
    __shared__ int   s_pidx[LF];
    __shared__ float s_pm[LF];
    __shared__ float red[256];

    for (int l = tid; l < LF; l += 256) {
        s_pidx[l] = item_pos_feedback[(size_t)b * LF + l];
        s_pm[l]   = pos_mask[(size_t)b * LF + l] ? 1.0f : 0.0f;
    }
    __syncthreads();

    int g = tid >> 6, e = tid & 63;
    float pacc = 0.0f;
    int base = g * 25;
    #pragma unroll 5
    for (int l = base; l < base + 25; l++)
        pacc += s_pm[l] * item_emb[(size_t)s_pidx[l] * E + e];
    red[tid] = pacc;
    __syncthreads();
    if (tid < 64) {
        float s = red[tid] + red[64 + tid] + red[128 + tid] + red[192 + tid];
        float cnt = 0.0f;
        #pragma unroll 10
        for (int l = 0; l < LF; l++) cnt += s_pm[l];
        g_prompt_input[b * E + tid] = s / cnt;
    }
}

// ======================================================================
// K1a v2: flash-style chunked attention (2 x 100), ~27 KB smem.
// ======================================================================
#define CSH 105
__global__ __launch_bounds__(256) void k1a_kernel(
    const float* __restrict__ item_emb, const float* __restrict__ user_emb,
    const int* __restrict__ user_id, const int* __restrict__ target_item_id,
    const int* __restrict__ history_item_id, const int* __restrict__ history_len)
{
    extern __shared__ float SHT[];   // [64][105]
    int b = blockIdx.x;
    int tid = threadIdx.x;

    __shared__ float s_tgt[E];
    __shared__ int   s_hidx[L];
    __shared__ float red[256];
    __shared__ float s_w[100];

    int tgt_id = target_item_id[b];
    if (tid < E) s_tgt[tid] = item_emb[(size_t)tgt_id * E + tid];
    for (int l = tid; l < L; l += 256) s_hidx[l] = history_item_id[(size_t)b * L + l];
    __syncthreads();

    int hlen = history_len[b];
    int g = tid >> 6, e = tid & 63;
    float accp = 0.0f;
    float m = -1e30f;
    float dsum = 0.0f;

    #pragma unroll
    for (int ch = 0; ch < 2; ch++) {
        for (int idx = tid; idx < 100 * 16; idx += 256) {
            int l = idx >> 4, c4 = idx & 15;
            float4 v = *(const float4*)(item_emb + (size_t)s_hidx[ch * 100 + l] * E + c4 * 4);
            SHT[(4*c4+0) * CSH + l] = v.x;
            SHT[(4*c4+1) * CSH + l] = v.y;
            SHT[(4*c4+2) * CSH + l] = v.z;
            SHT[(4*c4+3) * CSH + l] = v.w;
        }
        __syncthreads();

        float sc = -1e30f;
        if (tid < 100) {
            float d = 0.0f;
            #pragma unroll 8
            for (int e2 = 0; e2 < E; e2++)
                d += SHT[e2 * CSH + tid] * s_tgt[e2];
            int gl = ch * 100 + tid;
            sc = (gl < hlen) ? d * 0.125f : -1e9f;
        }
        red[tid] = sc; __syncthreads();
        for (int s = 128; s > 0; s >>= 1) { if (tid < s) red[tid] = fmaxf(red[tid], red[tid+s]); __syncthreads(); }
        float mnew = fmaxf(m, red[0]);
        __syncthreads();
        float wv = (tid < 100) ? expf(sc - mnew) : 0.0f;
        if (tid < 100) s_w[tid] = wv;
        red[tid] = wv; __syncthreads();
        for (int s = 128; s > 0; s >>= 1) { if (tid < s) red[tid] += red[tid+s]; __syncthreads(); }
        float wsum = red[0];
        __syncthreads();

        float scale = expf(m - mnew);
        dsum = dsum * scale + wsum;
        float a = 0.0f;
        int base = g * 25;
        #pragma unroll 5
        for (int l = base; l < base + 25; l++)
            a += s_w[l] * SHT[e * CSH + l];
        accp = accp * scale + a;
        m = mnew;
        __syncthreads();
    }

    red[tid] = accp;
    __syncthreads();
    if (tid < 64) {
        float hp = (red[tid] + red[64 + tid] + red[128 + tid] + red[192 + tid]) / dsum;
        int uid = user_id[b];
        g_final_user[b * E + tid] = user_emb[(size_t)uid * E + tid] + g_ufe[b * E + tid] + hp;
        g_final_item[b * E + tid] = item_emb[(size_t)tgt_id * E + tid] + g_ife[b * E + tid];
    }
}

// ======================================================================
// K2 v6: HMMA bf16-split GEMM, 4 row-groups per block (B tile reused 4x).
// grid (16, 25). Block covers 256 rows x 128 cols.
// ======================================================================
#define K2_AHI  0
#define K2_ALO  2304
#define K2_BHI  4608
#define K2_BLO  9216
#define K2_DYNW 13824   /* words = 55296 B */

__global__ __launch_bounds__(256) void k2_kernel(
    const float* __restrict__ Wp, const float* __restrict__ bp)
{
    extern __shared__ __align__(16) uint32_t SW[];
    int jb = blockIdx.y * 128;
    int tid = threadIdx.x;
    __shared__ float sbias[128];

    for (int idx = tid; idx < 32 * 128; idx += 256) {
        int kk = idx >> 7, n = idx & 127;
        int j = jb + n;
        float v0 = 0.0f, v1 = 0.0f;
        if (j < TPD) {
            v0 = Wp[(size_t)(2*kk)     * TPD + j];
            v1 = Wp[(size_t)(2*kk + 1) * TPD + j];
        }
        SW[K2_BHI + n * 36 + kk] = packbf(v0, v1);
        SW[K2_BLO + n * 36 + kk] = packbf(bflo(v0), bflo(v1));
    }
    if (tid < 128) {
        int j = jb + tid;
        sbias[tid] = (j < TPD) ? bp[j] : 0.0f;
    }

    int w = tid >> 5, lane = tid & 31;
    int g = lane >> 2, t = lane & 3;
    int mt = w & 3;
    int half = w >> 2;
    int R = mt * 16;

    #pragma unroll
    for (int rg = 0; rg < 4; rg++) {
        int b0 = (blockIdx.x * 4 + rg) * 64;
        if (rg) __syncthreads();
        for (int idx = tid; idx < 64 * 16; idx += 256) {
            int i = idx >> 4, c4 = idx & 15;
            float4 v = *(const float4*)&g_prompt_input[(b0 + i) * E + c4 * 4];
            int rb = i * 36 + 2 * c4;
            SW[K2_AHI + rb]     = packbf(v.x, v.y);
            SW[K2_AHI + rb + 1] = packbf(v.z, v.w);
            SW[K2_ALO + rb]     = packbf(bflo(v.x), bflo(v.y));
            SW[K2_ALO + rb + 1] = packbf(bflo(v.z), bflo(v.w));
        }
        __syncthreads();

        float acc[8][4];
        #pragma unroll
        for (int nt = 0; nt < 8; nt++)
            #pragma unroll
            for (int j = 0; j < 4; j++) acc[nt][j] = 0.0f;

        #pragma unroll
        for (int k = 0; k < 4; k++) {
            int o0 = (R + g) * 36 + 8*k + t;
            int o1 = (R + g + 8) * 36 + 8*k + t;
            uint32_t a0 = SW[K2_AHI + o0], a1 = SW[K2_AHI + o1];
            uint32_t a2 = SW[K2_AHI + o0 + 4], a3 = SW[K2_AHI + o1 + 4];
            uint32_t l0 = SW[K2_ALO + o0], l1 = SW[K2_ALO + o1];
            uint32_t l2 = SW[K2_ALO + o0 + 4], l3 = SW[K2_ALO + o1 + 4];
            #pragma unroll
            for (int nt = 0; nt < 8; nt++) {
                int n = half * 64 + nt * 8 + g;
                uint32_t b0r = SW[K2_BHI + n * 36 + 8*k + t];
                uint32_t b1r = SW[K2_BHI + n * 36 + 8*k + t + 4];
                uint32_t c0 = SW[K2_BLO + n * 36 + 8*k + t];
                uint32_t c1 = SW[K2_BLO + n * 36 + 8*k + t + 4];
                hmma(acc[nt], a0, a1, a2, a3, b0r, b1r);
                hmma(acc[nt], l0, l1, l2, l3, b0r, b1r);
                hmma(acc[nt], a0, a1, a2, a3, c0, c1);
            }
        }

        #pragma unroll
        for (int nt = 0; nt < 8; nt++) {
            int c = half * 64 + nt * 8 + 2 * t;
            int j = jb + c;
            if (j < TPD) {
                float bz0 = sbias[c], bz1 = sbias[c + 1];
                float2 v0, v1;
                v0.x = fmaxf(acc[nt][0] + bz0, 0.0f);
                v0.y = fmaxf(acc[nt][1] + bz1, 0.0f);
                v1.x = fmaxf(acc[nt][2] + bz0, 0.0f);
                v1.y = fmaxf(acc[nt][3] + bz1, 0.0f);
                *(float2*)&g_total_prompt[(size_t)(b0 + R + g) * TPD + j]     = v0;
                *(float2*)&g_total_prompt[(size_t)(b0 + R + g + 8) * TPD + j] = v1;
            }
        }
    }
}

// ======================================================================
// K3 v10 (restored): HMMA bf16-split, grid (B,2), streamed A chunks.
// Smem 32256 B -> 6 CTAs/SM.
// ======================================================================
#define ACH_LO  2016
#define HHI_W   0
#define HLO_W   2240
#define W1HI_W  4480
#define W1LO_W  5632
#define W2HI_W  6784
#define W2LO_W  7424
#define K3_DYNW 8064    /* words = 32256 B */

__global__ __launch_bounds__(256) void k3_kernel(
    const float* __restrict__ item_emb,
    const int* __restrict__ pos_fb, const int* __restrict__ pos_mask,
    const int* __restrict__ neg_fb, const int* __restrict__ neg_mask)
{
    extern __shared__ __align__(16) uint32_t SW[];
    int b  = blockIdx.x;
    int br = blockIdx.y;
    int tid = threadIdx.x;
    const float* tp = g_total_prompt + (size_t)b * TPD;

    __shared__ int   s_fi[112];
    __shared__ float s_fm[112];
    __shared__ float b1s[32], b2s[32];
    __shared__ float RED[7][32];

    const int* fb = br ? neg_fb : pos_fb;
    const int* mk = br ? neg_mask : pos_mask;
    if (tid < 112) {
        int v = 0; float m = 0.0f;
        if (tid < LF) { v = fb[(size_t)b * LF + tid]; m = mk[(size_t)b * LF + tid] ? 1.0f : 0.0f; }
        s_fi[tid] = v; s_fm[tid] = m;
    }
    if (tid < 32) { b1s[tid] = tp[2080 + tid]; b2s[tid] = tp[3136 + tid]; }

    for (int idx = tid; idx < 1024; idx += 256) {
        int h = idx & 31, ep = idx >> 5;
        float v0 = tp[32 + (2*ep)     * 32 + h];
        float v1 = tp[32 + (2*ep + 1) * 32 + h];
        SW[W1HI_W + h * 36 + ep] = packbf(v0, v1);
        SW[W1LO_W + h * 36 + ep] = packbf(bflo(v0), bflo(v1));
    }
    for (int idx = tid; idx < 512; idx += 256) {
        int p = idx & 31, hp = idx >> 5;
        float v0 = tp[2112 + (2*hp)     * 32 + p];
        float v1 = tp[2112 + (2*hp + 1) * 32 + p];
        SW[W2HI_W + p * 20 + hp] = packbf(v0, v1);
        SW[W2LO_W + p * 20 + hp] = packbf(bflo(v0), bflo(v1));
    }
    __syncthreads();

    int w = tid >> 5, lane = tid & 31;
    int g = lane >> 2, t = lane & 3;
    bool act = (w < 7);
    int R = w * 16;

    float acc1[4][4];
    #pragma unroll
    for (int nt = 0; nt < 4; nt++)
        #pragma unroll
        for (int j = 0; j < 4; j++) acc1[nt][j] = 0.0f;

    #pragma unroll
    for (int ch = 0; ch < 2; ch++) {
        if (ch) __syncthreads();
        for (int idx = tid; idx < 112 * 8; idx += 256) {
            int i = idx >> 3, c4 = idx & 7;
            float4 v = *(const float4*)(item_emb + (size_t)s_fi[i] * E + ch * 32 + c4 * 4);
            int rb = i * 18 + 2 * c4;
            SW[rb]     = packbf(v.x, v.y);
            SW[rb + 1] = packbf(v.z, v.w);
            SW[ACH_LO + rb]     = packbf(bflo(v.x), bflo(v.y));
            SW[ACH_LO + rb + 1] = packbf(bflo(v.z), bflo(v.w));
        }
        __syncthreads();

        if (act) {
            #pragma unroll
            for (int k = 0; k < 2; k++) {
                int o0 = (R + g) * 18 + 8*k + t;
                int o1 = (R + g + 8) * 18 + 8*k + t;
                uint32_t a0 = SW[o0], a1 = SW[o1];
                uint32_t a2 = SW[o0 + 4], a3 = SW[o1 + 4];
                uint32_t l0 = SW[ACH_LO + o0], l1 = SW[ACH_LO + o1];
                uint32_t l2 = SW[ACH_LO + o0 + 4], l3 = SW[ACH_LO + o1 + 4];
                int eo = 8 * (2 * ch + k) + t;
                #pragma unroll
                for (int nt = 0; nt < 4; nt++) {
                    int n = nt * 8 + g;
                    uint32_t b0 = SW[W1HI_W + n * 36 + eo];
                    uint32_t b1 = SW[W1HI_W + n * 36 + eo + 4];
                    uint32_t c0 = SW[W1LO_W + n * 36 + eo];
                    uint32_t c1 = SW[W1LO_W + n * 36 + eo + 4];
                    hmma(acc1[nt], a0, a1, a2, a3, b0, b1);
                    hmma(acc1[nt], l0, l1, l2, l3, b0, b1);
                    hmma(acc1[nt], a0, a1, a2, a3, c0, c1);
                }
            }
        }
    }
    __syncthreads();

    if (act) {
        #pragma unroll
        for (int nt = 0; nt < 4; nt++) {
            int c = nt * 8 + 2 * t;
            float h00 = fmaxf(acc1[nt][0] + b1s[c],     0.0f);
            float h01 = fmaxf(acc1[nt][1] + b1s[c + 1], 0.0f);
            float h10 = fmaxf(acc1[nt][2] + b1s[c],     0.0f);
            float h11 = fmaxf(acc1[nt][3] + b1s[c + 1], 0.0f);
            int w0 = (R + g) * 20 + nt * 4 + t;
            int w1 = (R + g + 8) * 20 + nt * 4 + t;
            SW[HHI_W + w0] = packbf(h00, h01);
            SW[HHI_W + w1] = packbf(h10, h11);
            SW[HLO_W + w0] = packbf(bflo(h00), bflo(h01));
            SW[HLO_W + w1] = packbf(bflo(h10), bflo(h11));
        }
    }
    __syncthreads();

    float acc2[4][4];
    #pragma unroll
    for (int nt = 0; nt < 4; nt++)
        #pragma unroll
        for (int j = 0; j < 4; j++) acc2[nt][j] = 0.0f;

    if (act) {
        #pragma unroll
        for (int k = 0; k < 2; k++) {
            int o0 = (R + g) * 20 + 8*k + t;
            int o1 = (R + g + 8) * 20 + 8*k + t;
            uint32_t a0 = SW[HHI_W + o0], a1 = SW[HHI_W + o1];
            uint32_t a2 = SW[HHI_W + o0 + 4], a3 = SW[HHI_W + o1 + 4];
            uint32_t l0 = SW[HLO_W + o0], l1 = SW[HLO_W + o1];
            uint32_t l2 = SW[HLO_W + o0 + 4], l3 = SW[HLO_W + o1 + 4];
            #pragma unroll
            for (int nt = 0; nt < 4; nt++) {
                int n = nt * 8 + g;
                uint32_t b0 = SW[W2HI_W + n * 20 + 8*k + t];
                uint32_t b1 = SW[W2HI_W + n * 20 + 8*k + t + 4];
                uint32_t c0 = SW[W2LO_W + n * 20 + 8*k + t];
                uint32_t c1 = SW[W2LO_W + n * 20 + 8*k + t + 4];
                hmma(acc2[nt], a0, a1, a2, a3, b0, b1);
                hmma(acc2[nt], l0, l1, l2, l3, b0, b1);
                hmma(acc2[nt], a0, a1, a2, a3, c0, c1);
            }
        }

        float m0 = s_fm[R + g], m1 = s_fm[R + g + 8];
        float part[4][2];
        #pragma unroll
        for (int nt = 0; nt < 4; nt++) {
            int c = nt * 8 + 2 * t;
            part[nt][0] = m0 * (acc2[nt][0] + b2s[c])   + m1 * (acc2[nt][2] + b2s[c]);
            part[nt][1] = m0 * (acc2[nt][1] + b2s[c+1]) + m1 * (acc2[nt][3] + b2s[c+1]);
        }
        #pragma unroll
        for (int s = 4; s <= 16; s <<= 1) {
            #pragma unroll
            for (int nt = 0; nt < 4; nt++) {
                part[nt][0] += __shfl_xor_sync(0xffffffffu, part[nt][0], s);
                part[nt][1] += __shfl_xor_sync(0xffffffffu, part[nt][1], s);
            }
        }
        if (lane < 4) {
            #pragma unroll
            for (int nt = 0; nt < 4; nt++) {
                RED[w][nt * 8 + 2 * lane]     = part[nt][0];
                RED[w][nt * 8 + 2 * lane + 1] = part[nt][1];
            }
        }
    }
    __syncthreads();
    if (tid < 32) {
        float pe = 0.0f;
        #pragma unroll
        for (int q = 0; q < 7; q++) pe += RED[q][tid];
        (br ? g_neg_pe : g_pos_pe)[b * 32 + tid] = pe;
    }
}

// ======================================================================
// K4: loss + fusion MLP + dot. 4 rows/block.
// ======================================================================
__global__ __launch_bounds__(256) void k4_kernel(
    const float* __restrict__ Wf1, const float* __restrict__ bf1,
    const float* __restrict__ Wf2, const float* __restrict__ bf2,
    const float* __restrict__ Wf3, float* __restrict__ out)
{
    int b0 = blockIdx.x * 4;
    int tid = threadIdx.x;
    __shared__ float fin[4 * 128];
    __shared__ float h1[4 * 200];
    __shared__ float h2[4 * 80];
    __shared__ float fu[4 * 64];

    if (tid < 128) {
        int r = tid >> 5, c = tid & 31;
        int bb = b0 + r;
        float pos = g_pos_pe[bb * 32 + c];
        float neg = g_neg_pe[bb * 32 + c];
        float x = neg - pos;
        out[B + bb * 32 + c] = fmaxf(x, 0.0f) + log1pf(expf(-fabsf(x)));
    }

    for (int t = tid; t < 4 * 128; t += 256) {
        int r = t >> 7, c = t & 127;
        int bb = b0 + r;
        float v;
        if (c < 64)      v = g_final_item[bb * 64 + c];
        else if (c < 96) v = g_pos_pe[bb * 32 + (c - 64)];
        else             v = g_total_prompt[(size_t)bb * TPD + (c - 96)];
        fin[t] = v;
    }
    __syncthreads();

    if (tid < 200) {
        float acc[4];
        #pragma unroll
        for (int r = 0; r < 4; r++) acc[r] = bf1[tid];
        #pragma unroll 4
        for (int k = 0; k < 128; k++) {
            float w = Wf1[k * 200 + tid];
            #pragma unroll
            for (int r = 0; r < 4; r++) acc[r] += fin[r * 128 + k] * w;
        }
        #pragma unroll
        for (int r = 0; r < 4; r++) h1[r * 200 + tid] = acc[r] > 0.0f ? acc[r] : 0.0f;
    }
    __syncthreads();

    if (tid < 80) {
        float acc[4];
        #pragma unroll
        for (int r = 0; r < 4; r++) acc[r] = bf2[tid];
        #pragma unroll 4
        for (int k = 0; k < 200; k++) {
            float w = Wf2[k * 80 + tid];
            #pragma unroll
            for (int r = 0; r < 4; r++) acc[r] += h1[r * 200 + k] * w;
        }
        #pragma unroll
        for (int r = 0; r < 4; r++) h2[r * 80 + tid] = acc[r] > 0.0f ? acc[r] : 0.0f;
    }
    __syncthreads();

    if (tid < 64) {
        float acc[4];
        #pragma unroll
        for (int r = 0; r < 4; r++) acc[r] = 0.0f;
        #pragma unroll 4
        for (int k = 0; k < 80; k++) {
            float w = Wf3[k * 64 + tid];
            #pragma unroll
            for (int r = 0; r < 4; r++) acc[r] += h2[r * 80 + k] * w;
        }
        #pragma unroll
        for (int r = 0; r < 4; r++) fu[r * 64 + tid] = acc[r];
    }
    __syncthreads();

    int r = tid >> 5, lane = tid & 31;
    if (r < 4) {
        int bb = b0 + r;
        float par = g_final_user[bb * 64 + lane]      * fu[r * 64 + lane]
                  + g_final_user[bb * 64 + 32 + lane] * fu[r * 64 + 32 + lane];
        #pragma unroll
        for (int s = 16; s > 0; s >>= 1) par += __shfl_xor_sync(0xffffffff, par, s);
        if (lane == 0) out[bb] = par;
    }
}

// ---------------- side stream + fork/join events ----------------
static cudaStream_t g_s2;
static cudaEvent_t  g_ev_fork, g_ev_join;
static bool g_init = []() {
    cudaStreamCreateWithFlags(&g_s2, cudaStreamNonBlocking);
    cudaEventCreateWithFlags(&g_ev_fork, cudaEventDisableTiming);
    cudaEventCreateWithFlags(&g_ev_join, cudaEventDisableTiming);
    return true;
}();

// ======================================================================
extern "C" void kernel_launch(void* const* d_in, const int* in_sizes, int n_in,
                              void* d_out, int out_size)
{
    const float* item_emb        = (const float*)d_in[0];
    const float* user_emb        = (const float*)d_in[1];
    const float* W_if            = (const float*)d_in[2];
    const float* b_if            = (const float*)d_in[3];
    const float* W_uf            = (const float*)d_in[4];
    const float* b_uf            = (const float*)d_in[5];
    const float* Wp              = (const float*)d_in[6];
    const float* bp              = (const float*)d_in[7];
    const float* Wf1             = (const float*)d_in[8];
    const float* bf1             = (const float*)d_in[9];
    const float* Wf2             = (const float*)d_in[10];
    const float* bf2             = (const float*)d_in[11];
    const float* Wf3             = (const float*)d_in[12];
    const float* item_features   = (const float*)d_in[13];
    const float* user_features   = (const float*)d_in[14];
    const int*   user_id         = (const int*)d_in[15];
    const int*   target_item_id  = (const int*)d_in[16];
    const int*   history_item_id = (const int*)d_in[17];
    const int*   history_len     = (const int*)d_in[18];
    const int*   pos_fb          = (const int*)d_in[19];
    const int*   pos_mask        = (const int*)d_in[20];
    const int*   neg_fb          = (const int*)d_in[21];
    const int*   neg_mask        = (const int*)d_in[22];
    float* out = (float*)d_out;

    const int k1a_dyn = 64 * CSH * sizeof(float);  // 26880 B
    const int k2_dyn  = K2_DYNW * 4;               // 55296 B
    const int k3_dyn  = K3_DYNW * 4;               // 32256 B
    cudaFuncSetAttribute(k1a_kernel, cudaFuncAttributeMaxDynamicSharedMemorySize, k1a_dyn);
    cudaFuncSetAttribute(k2_kernel,  cudaFuncAttributeMaxDynamicSharedMemorySize, k2_dyn);
    cudaFuncSetAttribute(k3_kernel,  cudaFuncAttributeMaxDynamicSharedMemorySize, k3_dyn);

    // fork: side chain {K0 -> K1a} runs concurrently with {K1p -> K2 -> K3}
    cudaEventRecord(g_ev_fork, 0);
    cudaStreamWaitEvent(g_s2, g_ev_fork, 0);

    k0_kernel<<<B / 32, 256, 0, g_s2>>>(item_features, user_features, W_if, b_if, W_uf, b_uf);
    k1a_kernel<<<B, 256, k1a_dyn, g_s2>>>(item_emb, user_emb, user_id, target_item_id,
                                          history_item_id, history_len);
    cudaEventRecord(g_ev_join, g_s2);

    k1p_kernel<<<B, 256>>>(item_emb, pos_fb, pos_mask);
    k2_kernel<<<dim3(16, 25), 256, k2_dyn>>>(Wp, bp);
    k3_kernel<<<dim3(B, 2), 256, k3_dyn>>>(item_emb, pos_fb, pos_mask, neg_fb, neg_mask);

    // join: K4 needs both chains
    cudaStreamWaitEvent(0, g_ev_join, 0);
    k4_kernel<<<B / 4, 256>>>(Wf1, bf1, Wf2, bf2, Wf3, out);
}